// round 1
// baseline (speedup 1.0000x reference)
#include <cuda_runtime.h>

// Problem constants
#define HID 64
#define GATES 192          // 3*HID
#define BATCH 4096
#define TSTEPS 512
#define TILE_B 32
#define NCTA (BATCH / TILE_B)   // 128
#define NTHREADS 256

// smem layout (in floats)
#define OFF_WR0   0              // Whh0^T  [64][192]
#define OFF_WA    12288          // Wih1^T  [64][192]
#define OFF_WB    24576          // Whh1^T  [64][192]
#define OFF_H0    36864          // h0 state [64][32]  (k-major)
#define OFF_H1    38912          // h1 state [64][32]
#define OFF_HGA   40960          // pre-activations A [192][32]
#define OFF_HGB   47104          // pre-activations B [192][32]
#define OFF_WIH0  53248          // Wih0 col-major [2][192]
#define OFF_BIH0  53632
#define OFF_BHH0  53824
#define OFF_BIH1  54016
#define OFF_BHH1  54208
#define OFF_WP    54400          // [128]
#define OFF_XS    54528          // x staging [64]: x0 at [b], x1 at [32+b]
#define SMEM_FLOATS 54592
#define SMEM_BYTES (SMEM_FLOATS * 4)   // 218368 B < 227KB opt-in limit

__device__ __forceinline__ float sigmoidf_(float v) {
    return 1.0f / (1.0f + __expf(-v));
}

extern __shared__ float smem[];

__global__ void __launch_bounds__(NTHREADS, 1)
gru2_fused_kernel(const float* __restrict__ x,
                  const float* __restrict__ Wih0, const float* __restrict__ Whh0,
                  const float* __restrict__ bih0, const float* __restrict__ bhh0,
                  const float* __restrict__ Wih1, const float* __restrict__ Whh1,
                  const float* __restrict__ bih1, const float* __restrict__ bhh1,
                  const float* __restrict__ Wp,   const float* __restrict__ bp,
                  float* __restrict__ out)
{
    const int tid = threadIdx.x;
    const int b0  = blockIdx.x * TILE_B;

    float* Wr0   = smem + OFF_WR0;
    float* WA    = smem + OFF_WA;
    float* WB    = smem + OFF_WB;
    float* h0s   = smem + OFF_H0;
    float* h1s   = smem + OFF_H1;
    float* hgA   = smem + OFF_HGA;
    float* hgB   = smem + OFF_HGB;
    float* wih0s = smem + OFF_WIH0;
    float* bih0s = smem + OFF_BIH0;
    float* bhh0s = smem + OFF_BHH0;
    float* bih1s = smem + OFF_BIH1;
    float* bhh1s = smem + OFF_BHH1;
    float* wps   = smem + OFF_WP;
    float* xs    = smem + OFF_XS;

    // ---- one-time: stage weights (transposed to k-major), biases, zero states
    for (int d = tid; d < HID * GATES; d += NTHREADS) {
        int k = d / GATES, g = d % GATES;
        Wr0[d] = Whh0[g * HID + k];
        WA[d]  = Wih1[g * HID + k];
        WB[d]  = Whh1[g * HID + k];
    }
    for (int g = tid; g < GATES; g += NTHREADS) {
        wih0s[g]         = Wih0[g * 2 + 0];
        wih0s[GATES + g] = Wih0[g * 2 + 1];
        bih0s[g] = bih0[g];
        bhh0s[g] = bhh0[g];
        bih1s[g] = bih1[g];
        bhh1s[g] = bhh1[g];
    }
    if (tid < 2 * HID) wps[tid] = Wp[tid];
    for (int d = tid; d < HID * TILE_B; d += NTHREADS) { h0s[d] = 0.0f; h1s[d] = 0.0f; }
    __syncthreads();

    // GEMM thread tiling: 8 batch-groups (of 4) x 32 gate-groups (of 6)
    // Within a warp: bg = lane%8 (fast), gg = 4 distinct values -> weight LDS broadcast.
    const int bg = tid & 7;
    const int gg = tid >> 3;
    const int bb = bg * 4;        // batch offset in tile
    const int g0 = gg * 6;        // gate offset

    // gate-phase mapping: b = lane, j varies per warp -> conflict-free rows
    const int gb  = tid & 31;
    const int gj0 = tid >> 5;     // 0..7

    for (int t = 0; t < TSTEPS; ++t) {
        // stage x[t] for this tile (read in gate phase L0, after next barrier)
        if (tid < TILE_B) {
            const float* xp = x + ((size_t)t * BATCH + b0 + tid) * 2;
            xs[tid]          = xp[0];
            xs[TILE_B + tid] = xp[1];
        }

        // ---- GEMM1: hgA = h0 @ Whh0^T + bhh0   [32 x 192]
        {
            float acc[6][4];
            #pragma unroll
            for (int j = 0; j < 6; ++j) {
                float bv = bhh0s[g0 + j];
                acc[j][0] = bv; acc[j][1] = bv; acc[j][2] = bv; acc[j][3] = bv;
            }
            #pragma unroll 4
            for (int k = 0; k < HID; ++k) {
                float4 h4 = *(const float4*)(h0s + k * TILE_B + bb);
                const float* wr = Wr0 + k * GATES + g0;
                #pragma unroll
                for (int j = 0; j < 6; ++j) {
                    float w = wr[j];
                    acc[j][0] = fmaf(w, h4.x, acc[j][0]);
                    acc[j][1] = fmaf(w, h4.y, acc[j][1]);
                    acc[j][2] = fmaf(w, h4.z, acc[j][2]);
                    acc[j][3] = fmaf(w, h4.w, acc[j][3]);
                }
            }
            #pragma unroll
            for (int j = 0; j < 6; ++j)
                *(float4*)(hgA + (g0 + j) * TILE_B + bb) =
                    make_float4(acc[j][0], acc[j][1], acc[j][2], acc[j][3]);
        }
        __syncthreads();

        // ---- gates layer 0: h0 <- GRU(xg0(x,Wih0), hgA, h0)
        {
            float x0v = xs[gb];
            float x1v = xs[TILE_B + gb];
            #pragma unroll
            for (int i = 0; i < 8; ++i) {
                int j = i * 8 + gj0;
                float xr = fmaf(x1v, wih0s[GATES + j],
                            fmaf(x0v, wih0s[j], bih0s[j]));
                float xz = fmaf(x1v, wih0s[GATES + 64 + j],
                            fmaf(x0v, wih0s[64 + j], bih0s[64 + j]));
                float xn = fmaf(x1v, wih0s[GATES + 128 + j],
                            fmaf(x0v, wih0s[128 + j], bih0s[128 + j]));
                float hr = hgA[(j      ) * TILE_B + gb];
                float hz = hgA[(64  + j) * TILE_B + gb];
                float hn = hgA[(128 + j) * TILE_B + gb];
                float r = sigmoidf_(xr + hr);
                float z = sigmoidf_(xz + hz);
                float n = tanhf(fmaf(r, hn, xn));
                float hp = h0s[j * TILE_B + gb];
                h0s[j * TILE_B + gb] = fmaf(z, hp - n, n);   // (1-z)*n + z*h
            }
        }
        __syncthreads();

        // ---- GEMM2: hgA = h0new @ Wih1^T + bih1 ; hgB = h1 @ Whh1^T + bhh1
        {
            float accA[6][4], accB[6][4];
            #pragma unroll
            for (int j = 0; j < 6; ++j) {
                float ba = bih1s[g0 + j], bb2 = bhh1s[g0 + j];
                accA[j][0] = ba; accA[j][1] = ba; accA[j][2] = ba; accA[j][3] = ba;
                accB[j][0] = bb2; accB[j][1] = bb2; accB[j][2] = bb2; accB[j][3] = bb2;
            }
            #pragma unroll 2
            for (int k = 0; k < HID; ++k) {
                float4 a4 = *(const float4*)(h0s + k * TILE_B + bb);
                float4 c4 = *(const float4*)(h1s + k * TILE_B + bb);
                const float* wa = WA + k * GATES + g0;
                const float* wb = WB + k * GATES + g0;
                #pragma unroll
                for (int j = 0; j < 6; ++j) {
                    float w1 = wa[j], w2 = wb[j];
                    accA[j][0] = fmaf(w1, a4.x, accA[j][0]);
                    accA[j][1] = fmaf(w1, a4.y, accA[j][1]);
                    accA[j][2] = fmaf(w1, a4.z, accA[j][2]);
                    accA[j][3] = fmaf(w1, a4.w, accA[j][3]);
                    accB[j][0] = fmaf(w2, c4.x, accB[j][0]);
                    accB[j][1] = fmaf(w2, c4.y, accB[j][1]);
                    accB[j][2] = fmaf(w2, c4.z, accB[j][2]);
                    accB[j][3] = fmaf(w2, c4.w, accB[j][3]);
                }
            }
            #pragma unroll
            for (int j = 0; j < 6; ++j) {
                *(float4*)(hgA + (g0 + j) * TILE_B + bb) =
                    make_float4(accA[j][0], accA[j][1], accA[j][2], accA[j][3]);
                *(float4*)(hgB + (g0 + j) * TILE_B + bb) =
                    make_float4(accB[j][0], accB[j][1], accB[j][2], accB[j][3]);
            }
        }
        __syncthreads();

        // ---- gates layer 1: h1 <- GRU(hgA (=xg1), hgB (=hg1), h1)
        {
            #pragma unroll
            for (int i = 0; i < 8; ++i) {
                int j = i * 8 + gj0;
                float ar = hgA[(j      ) * TILE_B + gb];
                float az = hgA[(64  + j) * TILE_B + gb];
                float an = hgA[(128 + j) * TILE_B + gb];
                float br = hgB[(j      ) * TILE_B + gb];
                float bz = hgB[(64  + j) * TILE_B + gb];
                float bn = hgB[(128 + j) * TILE_B + gb];
                float r = sigmoidf_(ar + br);
                float z = sigmoidf_(az + bz);
                float n = tanhf(fmaf(r, bn, an));
                float hp = h1s[j * TILE_B + gb];
                h1s[j * TILE_B + gb] = fmaf(z, hp - n, n);
            }
        }
        __syncthreads();
    }

    // ---- final projection: out[b] = [h0f, h1f] . Wp + bp
    if (tid < TILE_B) {
        float s = bp[0];
        #pragma unroll 8
        for (int k = 0; k < HID; ++k) s = fmaf(h0s[k * TILE_B + tid], wps[k], s);
        #pragma unroll 8
        for (int k = 0; k < HID; ++k) s = fmaf(h1s[k * TILE_B + tid], wps[HID + k], s);
        out[b0 + tid] = s;
    }
}

extern "C" void kernel_launch(void* const* d_in, const int* in_sizes, int n_in,
                              void* d_out, int out_size) {
    const float* x    = (const float*)d_in[0];
    const float* Wih0 = (const float*)d_in[1];
    const float* Whh0 = (const float*)d_in[2];
    const float* bih0 = (const float*)d_in[3];
    const float* bhh0 = (const float*)d_in[4];
    const float* Wih1 = (const float*)d_in[5];
    const float* Whh1 = (const float*)d_in[6];
    const float* bih1 = (const float*)d_in[7];
    const float* bhh1 = (const float*)d_in[8];
    const float* Wp   = (const float*)d_in[9];
    const float* bp   = (const float*)d_in[10];
    float* out = (float*)d_out;

    cudaFuncSetAttribute(gru2_fused_kernel,
                         cudaFuncAttributeMaxDynamicSharedMemorySize, SMEM_BYTES);
    gru2_fused_kernel<<<NCTA, NTHREADS, SMEM_BYTES>>>(
        x, Wih0, Whh0, bih0, bhh0, Wih1, Whh1, bih1, bhh1, Wp, bp, out);
}